// round 11
// baseline (speedup 1.0000x reference)
#include <cuda_runtime.h>
#include <cuda_bf16.h>
#include <math.h>

#define Bn 32
#define Sn 2048
#define Hn 1024
#define TEMP 0.07f
#define EPSL 1e-8f

// ---------------- device scratch (static, no allocation) ----------------
__device__ float g_wa[Bn * Sn];
__device__ float g_wo[Bn * Sn];
__device__ float g_pa[Bn * 32 * Hn];
__device__ float g_po[Bn * 32 * Hn];
__device__ float g_aemb[Bn * Hn];
__device__ float g_oemb[Bn * Hn];
__device__ float g_sin[Bn * 2 * Hn];
__device__ float g_gp[3145728];        // gemm partials: 3 regions (12MB)
__device__ float g_ha[Bn * 512];
__device__ float g_ho[Bn * 512];
__device__ float g_hs[Bn * 1024];
__device__ float g_za[Bn * 128];
__device__ float g_zo[Bn * 128];
__device__ float g_zs[Bn * 256];

#define G0OFF 0
#define G1OFF 524288
#define G2OFF 1048576

// ---------------- kernel 1: softmax weights over S ----------------
__global__ void k_softmax_w(const float* __restrict__ la,
                            const float* __restrict__ lo,
                            float* __restrict__ wa, float* __restrict__ wo) {
    int b = blockIdx.x;
    const float* L = blockIdx.y ? lo : la;
    float* W = blockIdx.y ? wo : wa;
    __shared__ float sc[Sn];
    __shared__ float red[16];
    int tid = threadIdx.x;           // 256 threads
    int lane = tid & 31, wid = tid >> 5;

    float m = -1e30f;
    for (int s = tid; s < Sn; s += 256) {
        const float* p = L + ((size_t)b * Sn + s) * 5;
        float v = p[1] + p[2] + p[3] + p[4];
        sc[s] = v;
        m = fmaxf(m, v);
    }
    #pragma unroll
    for (int o2 = 16; o2; o2 >>= 1) m = fmaxf(m, __shfl_xor_sync(0xffffffffu, m, o2));
    if (lane == 0) red[wid] = m;
    __syncthreads();
    if (tid == 0) {
        float mm = red[0];
        for (int w = 1; w < 8; w++) mm = fmaxf(mm, red[w]);
        red[8] = mm;
    }
    __syncthreads();
    m = red[8];
    __syncthreads();

    float sum = 0.f;
    for (int s = tid; s < Sn; s += 256) {
        float e = expf(sc[s] - m);
        sc[s] = e;
        sum += e;
    }
    #pragma unroll
    for (int o2 = 16; o2; o2 >>= 1) sum += __shfl_xor_sync(0xffffffffu, sum, o2);
    if (lane == 0) red[wid] = sum;
    __syncthreads();
    if (tid == 0) {
        float ss = 0.f;
        for (int w = 0; w < 8; w++) ss += red[w];
        red[9] = ss;
    }
    __syncthreads();
    float inv = 1.0f / red[9];
    for (int s = tid; s < Sn; s += 256) W[(size_t)b * Sn + s] = sc[s] * inv;
}

// ---------------- kernel 2: pooling partials (256MB streaming pass) ----------------
__global__ void k_pool_partial(const float* __restrict__ span,
                               const float* __restrict__ wa,
                               const float* __restrict__ wo,
                               float* __restrict__ pa, float* __restrict__ po) {
    int sc = blockIdx.x, b = blockIdx.y;
    __shared__ float swa[64], swo[64];
    int tid = threadIdx.x;  // 256
    if (tid < 64) swa[tid] = wa[(size_t)b * Sn + sc * 64 + tid];
    else if (tid < 128) { int t = tid - 64; swo[t] = wo[(size_t)b * Sn + sc * 64 + t]; }
    __syncthreads();

    const float4* base = (const float4*)(span + ((size_t)b * Sn + (size_t)sc * 64) * Hn);
    float4 aa = make_float4(0.f, 0.f, 0.f, 0.f);
    float4 oo = make_float4(0.f, 0.f, 0.f, 0.f);
    #pragma unroll 16
    for (int s = 0; s < 64; s++) {
        float4 v = __ldcs(base + (size_t)s * 256 + tid);   // streaming, evict-first
        float fa = swa[s], fo = swo[s];
        aa.x += v.x * fa; aa.y += v.y * fa; aa.z += v.z * fa; aa.w += v.w * fa;
        oo.x += v.x * fo; oo.y += v.y * fo; oo.z += v.z * fo; oo.w += v.w * fo;
    }
    size_t off = ((size_t)b * 32 + sc) * Hn + tid * 4;
    *(float4*)(pa + off) = aa;
    *(float4*)(po + off) = oo;
}

// ---------------- kernel 3: reduce partials -> embeddings + concat ----------------
__global__ void k_pool_reduce(const float* __restrict__ pa, const float* __restrict__ po,
                              float* __restrict__ aemb, float* __restrict__ oemb,
                              float* __restrict__ sin_) {
    int idx = blockIdx.x * 256 + threadIdx.x;  // 32768 total
    int b = idx >> 10, h = idx & 1023;
    float sa = 0.f, so = 0.f;
    #pragma unroll 8
    for (int c = 0; c < 32; c++) {
        sa += pa[((size_t)b * 32 + c) * Hn + h];
        so += po[((size_t)b * 32 + c) * Hn + h];
    }
    aemb[idx] = sa;
    oemb[idx] = so;
    sin_[(size_t)b * 2048 + h] = sa;
    sin_[(size_t)b * 2048 + 1024 + h] = so;
}

// ---------------- kernel 4: register-tiled MLP GEMM, 32k x 64j tiles ----------------
// j-tile 64: doubles block count vs 128-wide tiles with NO extra W/partial
// traffic. Block: 32b x 64j over a 32-wide k-chunk, 256 threads, thread=4b x 2j.
struct GA { const float* x; const float* W; float* part; int K; int N; };

__global__ void __launch_bounds__(256) k_mlp_gemm(GA a0, GA a1, GA a2, int n0, int n01) {
    int bx = blockIdx.x;
    GA g;
    if (bx < n0) g = a0;
    else if (bx < n01) { g = a1; bx -= n0; }
    else { g = a2; bx -= n01; }
    int jt = g.N >> 6;             // 64-wide j-tiles
    int jtile = bx % jt;
    int kch   = bx / jt;
    int tid  = threadIdx.x;        // 256
    int lane = tid & 31;
    int wrp  = tid >> 5;           // 0..7, owns b rows [4w, 4w+4)
    int b0 = wrp << 2;
    int j  = (jtile << 6) + (lane << 1);
    int k0 = kch << 5;

    __shared__ float xs[32][33];   // xs[k][b], padded
    {
        int idx = tid;             // 256 threads cover 32x32 in 4 steps
        #pragma unroll
        for (int r = 0; r < 4; r++, idx += 256) {
            int b = idx >> 5, kk = idx & 31;
            xs[kk][b] = g.x[(size_t)b * g.K + k0 + kk];
        }
    }
    __syncthreads();

    float acc[4][2];
    #pragma unroll
    for (int bi = 0; bi < 4; bi++) { acc[bi][0] = 0.f; acc[bi][1] = 0.f; }

    const float2* __restrict__ Wp = (const float2*)(g.W + (size_t)k0 * g.N + j);
    size_t stride2 = (size_t)(g.N >> 1);

    #pragma unroll
    for (int kk = 0; kk < 32; kk += 8) {
        float2 w[8];
        #pragma unroll
        for (int u = 0; u < 8; u++)
            w[u] = __ldg(Wp + (size_t)(kk + u) * stride2);   // default policy: L2-resident
        #pragma unroll
        for (int u = 0; u < 8; u++) {
            int k = kk + u;
            float xv0 = xs[k][b0 + 0];
            float xv1 = xs[k][b0 + 1];
            float xv2 = xs[k][b0 + 2];
            float xv3 = xs[k][b0 + 3];
            acc[0][0] += xv0 * w[u].x; acc[0][1] += xv0 * w[u].y;
            acc[1][0] += xv1 * w[u].x; acc[1][1] += xv1 * w[u].y;
            acc[2][0] += xv2 * w[u].x; acc[2][1] += xv2 * w[u].y;
            acc[3][0] += xv3 * w[u].x; acc[3][1] += xv3 * w[u].y;
        }
    }

    float* pp = g.part + (size_t)(kch * 32) * g.N + j;
    #pragma unroll
    for (int bi = 0; bi < 4; bi++) {
        float2 v = make_float2(acc[bi][0], acc[bi][1]);
        *(float2*)(pp + (size_t)(b0 + bi) * g.N) = v;
    }
}

// ---------------- kernel 5: combine partials + bias (+relu), float4 ----------------
struct CA { const float* part; const float* bias; float* out; int N; int kc; };

__global__ void k_combine(CA c0, CA c1, CA c2, int relu) {
    int idx = blockIdx.x * 256 + threadIdx.x;        // vec4 index
    int n0 = 32 * (c0.N >> 2), n1 = 32 * (c1.N >> 2), n2 = 32 * (c2.N >> 2);
    CA c;
    int li;
    if (idx < n0) { c = c0; li = idx; }
    else if (idx < n0 + n1) { c = c1; li = idx - n0; }
    else if (idx < n0 + n1 + n2) { c = c2; li = idx - n0 - n1; }
    else return;
    int nv = c.N >> 2;
    int b = li / nv, jv = li % nv;
    const float4* bias4 = (const float4*)c.bias;
    const float4* part4 = (const float4*)c.part;
    float4 s = bias4[jv];
    #pragma unroll 8
    for (int ch = 0; ch < c.kc; ch++) {
        float4 p = part4[(size_t)(ch * 32 + b) * nv + jv];
        s.x += p.x; s.y += p.y; s.z += p.z; s.w += p.w;
    }
    if (relu) {
        s.x = fmaxf(s.x, 0.f); s.y = fmaxf(s.y, 0.f);
        s.z = fmaxf(s.z, 0.f); s.w = fmaxf(s.w, 0.f);
    }
    ((float4*)c.out)[li] = s;
}

// ---------------- kernel 6: fused losses (InfoNCE + NT-Xent), 1 block ----------------
__global__ void k_loss(const float* __restrict__ za, const float* __restrict__ zo,
                       const float* __restrict__ zs, const int* __restrict__ labels,
                       float* __restrict__ out) {
    __shared__ float a[32][128];
    __shared__ float o[32][129];
    __shared__ float s[32][257];
    __shared__ int lab[32];
    __shared__ float rowv[32];
    __shared__ float hasv[32];
    __shared__ float infv;
    int tid = threadIdx.x;
    int i = tid >> 5, j = tid & 31;

    for (int idx = tid; idx < 32 * 128; idx += 1024) a[idx >> 7][idx & 127] = za[idx];
    for (int idx = tid; idx < 32 * 128; idx += 1024) o[idx >> 7][idx & 127] = zo[idx];
    for (int idx = tid; idx < 32 * 256; idx += 1024) s[idx >> 8][idx & 255] = zs[idx];
    if (tid < 32) lab[tid] = labels[tid];
    __syncthreads();

    {
        float sa = 0.f, so = 0.f;
        #pragma unroll
        for (int t = 0; t < 4; t++) {
            float va = a[i][j + 32 * t]; sa += va * va;
            float vo = o[i][j + 32 * t]; so += vo * vo;
        }
        #pragma unroll
        for (int o2 = 16; o2; o2 >>= 1) {
            sa += __shfl_xor_sync(0xffffffffu, sa, o2);
            so += __shfl_xor_sync(0xffffffffu, so, o2);
        }
        float ia = 1.0f / fmaxf(sqrtf(sa), 1e-12f);
        float io = 1.0f / fmaxf(sqrtf(so), 1e-12f);
        #pragma unroll
        for (int t = 0; t < 4; t++) {
            a[i][j + 32 * t] *= ia;
            o[i][j + 32 * t] *= io;
        }
        float ss = 0.f;
        #pragma unroll
        for (int t = 0; t < 8; t++) { float v = s[i][j + 32 * t]; ss += v * v; }
        #pragma unroll
        for (int o2 = 16; o2; o2 >>= 1) ss += __shfl_xor_sync(0xffffffffu, ss, o2);
        float inv = 1.0f / fmaxf(sqrtf(ss), 1e-12f);
        #pragma unroll
        for (int t = 0; t < 8; t++) s[i][j + 32 * t] *= inv;
    }
    __syncthreads();

    // ---- InfoNCE ----
    {
        float d = 0.f;
        #pragma unroll 8
        for (int k = 0; k < 128; k++) d += a[i][k] * o[j][k];
        float e = expf(d * (1.0f / TEMP));
        bool same = (lab[i] == lab[j]);
        float pm = (i == j) ? 1.0f : (same ? 0.5f : 0.0f);
        float num = e * pm, den = e;
        #pragma unroll
        for (int o2 = 16; o2; o2 >>= 1) {
            num += __shfl_xor_sync(0xffffffffu, num, o2);
            den += __shfl_xor_sync(0xffffffffu, den, o2);
        }
        if (j == 0) rowv[i] = -logf(num / den + EPSL);
    }
    __syncthreads();
    if (tid == 0) {
        float sm = 0.f;
        for (int r = 0; r < 32; r++) sm += rowv[r];
        infv = sm * (1.0f / 32.0f);
    }
    __syncthreads();

    // ---- NT-Xent ----
    {
        float d = 0.f;
        #pragma unroll 8
        for (int k = 0; k < 256; k++) d += s[i][k] * s[j][k];
        float e = expf(d * (1.0f / TEMP));
        bool same = (lab[i] == lab[j]);
        float maskv = (same && (i != j)) ? 1.0f : 0.0f;
        float pos = e * maskv;
        float neg = e * (1.0f - maskv);
        float cnt = maskv;
        #pragma unroll
        for (int o2 = 16; o2; o2 >>= 1) {
            pos += __shfl_xor_sync(0xffffffffu, pos, o2);
            neg += __shfl_xor_sync(0xffffffffu, neg, o2);
            cnt += __shfl_xor_sync(0xffffffffu, cnt, o2);
        }
        if (j == 0) {
            if (cnt > 0.f) {
                rowv[i] = -logf(pos / (pos + neg) + EPSL) / fmaxf(cnt, 1.0f);
                hasv[i] = 1.0f;
            } else {
                rowv[i] = 0.f;
                hasv[i] = 0.f;
            }
        }
    }
    __syncthreads();
    if (tid == 0) {
        float sr = 0.f, sh = 0.f;
        for (int r = 0; r < 32; r++) { sr += rowv[r]; sh += hasv[r]; }
        float nt = sr / fmaxf(sh, 1.0f);
        out[0] = infv + 0.5f * nt;
    }
}

// ---------------- host launch ----------------
extern "C" void kernel_launch(void* const* d_in, const int* in_sizes, int n_in,
                              void* d_out, int out_size) {
    const float* span = (const float*)d_in[0];
    const float* la   = (const float*)d_in[1];
    const float* lo   = (const float*)d_in[2];
    const int*   lab  = (const int*)  d_in[3];
    const float* Wa1  = (const float*)d_in[4];
    const float* ba1  = (const float*)d_in[5];
    const float* Wa2  = (const float*)d_in[6];
    const float* ba2  = (const float*)d_in[7];
    const float* Wo1  = (const float*)d_in[8];
    const float* bo1  = (const float*)d_in[9];
    const float* Wo2  = (const float*)d_in[10];
    const float* bo2  = (const float*)d_in[11];
    const float* Ws1  = (const float*)d_in[12];
    const float* bs1  = (const float*)d_in[13];
    const float* Ws2  = (const float*)d_in[14];
    const float* bs2  = (const float*)d_in[15];
    float* out = (float*)d_out;

    float *p_wa, *p_wo, *p_pa, *p_po, *p_ae, *p_oe, *p_si, *p_gp;
    float *p_ha, *p_ho, *p_hs, *p_za, *p_zo, *p_zs;
    cudaGetSymbolAddress((void**)&p_wa, g_wa);
    cudaGetSymbolAddress((void**)&p_wo, g_wo);
    cudaGetSymbolAddress((void**)&p_pa, g_pa);
    cudaGetSymbolAddress((void**)&p_po, g_po);
    cudaGetSymbolAddress((void**)&p_ae, g_aemb);
    cudaGetSymbolAddress((void**)&p_oe, g_oemb);
    cudaGetSymbolAddress((void**)&p_si, g_sin);
    cudaGetSymbolAddress((void**)&p_gp, g_gp);
    cudaGetSymbolAddress((void**)&p_ha, g_ha);
    cudaGetSymbolAddress((void**)&p_ho, g_ho);
    cudaGetSymbolAddress((void**)&p_hs, g_hs);
    cudaGetSymbolAddress((void**)&p_za, g_za);
    cudaGetSymbolAddress((void**)&p_zo, g_zo);
    cudaGetSymbolAddress((void**)&p_zs, g_zs);

    // 1. softmax pooling weights
    k_softmax_w<<<dim3(32, 2), 256>>>(la, lo, p_wa, p_wo);

    // 2. pooled embeddings: one pass over the 256MB span tensor
    k_pool_partial<<<dim3(32, 32), 256>>>(span, p_wa, p_wo, p_pa, p_po);
    k_pool_reduce<<<128, 256>>>(p_pa, p_po, p_ae, p_oe, p_si);

    // 3. layer-1 GEMMs in one flattened launch (relu in combine)
    {
        GA a0 = {p_ae, Wa1, p_gp + G0OFF, 1024, 512};   // kc=32, jt=8 -> 256 blocks
        GA a1 = {p_oe, Wo1, p_gp + G1OFF, 1024, 512};   // 256
        GA a2 = {p_si, Ws1, p_gp + G2OFF, 2048, 1024};  // kc=64, jt=16 -> 1024
        k_mlp_gemm<<<1536, 256>>>(a0, a1, a2, 256, 512);
        CA c0 = {p_gp + G0OFF, ba1, p_ha, 512, 32};
        CA c1 = {p_gp + G1OFF, bo1, p_ho, 512, 32};
        CA c2 = {p_gp + G2OFF, bs1, p_hs, 1024, 64};
        k_combine<<<64, 256>>>(c0, c1, c2, 1);
    }

    // 4. layer-2 GEMMs in one flattened launch (bias only)
    {
        GA a0 = {p_ha, Wa2, p_gp + G0OFF, 512, 128};    // kc=16, jt=2 -> 32
        GA a1 = {p_ho, Wo2, p_gp + G1OFF, 512, 128};    // 32
        GA a2 = {p_hs, Ws2, p_gp + G2OFF, 1024, 256};   // kc=32, jt=4 -> 128
        k_mlp_gemm<<<192, 256>>>(a0, a1, a2, 32, 64);
        CA c0 = {p_gp + G0OFF, ba2, p_za, 128, 16};
        CA c1 = {p_gp + G1OFF, bo2, p_zo, 128, 16};
        CA c2 = {p_gp + G2OFF, bs2, p_zs, 256, 32};
        k_combine<<<16, 256>>>(c0, c1, c2, 0);
    }

    // 5. fused losses
    k_loss<<<1, 1024>>>(p_za, p_zo, p_zs, lab, out);
}

// round 12
// speedup vs baseline: 1.0870x; 1.0870x over previous
#include <cuda_runtime.h>
#include <cuda_bf16.h>
#include <math.h>

#define Bn 32
#define Sn 2048
#define Hn 1024
#define TEMP 0.07f
#define EPSL 1e-8f
#define NCH 16

// ---------------- device scratch (static, no allocation) ----------------
__device__ float g_wa[Bn * Sn];
__device__ float g_wo[Bn * Sn];
__device__ float g_pa[Bn * NCH * Hn];
__device__ float g_po[Bn * NCH * Hn];
__device__ float g_aemb[Bn * Hn];
__device__ float g_oemb[Bn * Hn];
__device__ float g_sin[Bn * 2 * Hn];
__device__ float g_gp[3145728];        // gemm partials: 3 regions (12MB)
__device__ float g_ha[Bn * 512];
__device__ float g_ho[Bn * 512];
__device__ float g_hs[Bn * 1024];
__device__ float g_za[Bn * 128];
__device__ float g_zo[Bn * 128];
__device__ float g_zs[Bn * 256];
__device__ float g_res[2];             // [0]=infonce, [1]=ntxent

#define G0OFF 0
#define G1OFF 524288
#define G2OFF 1048576

// ---------------- kernel 1: softmax weights over S ----------------
__global__ void k_softmax_w(const float* __restrict__ la,
                            const float* __restrict__ lo,
                            float* __restrict__ wa, float* __restrict__ wo) {
    int b = blockIdx.x;
    const float* L = blockIdx.y ? lo : la;
    float* W = blockIdx.y ? wo : wa;
    __shared__ float sc[Sn];
    __shared__ float red[16];
    int tid = threadIdx.x;           // 256 threads
    int lane = tid & 31, wid = tid >> 5;

    float m = -1e30f;
    for (int s = tid; s < Sn; s += 256) {
        const float* p = L + ((size_t)b * Sn + s) * 5;
        float v = p[1] + p[2] + p[3] + p[4];
        sc[s] = v;
        m = fmaxf(m, v);
    }
    #pragma unroll
    for (int o2 = 16; o2; o2 >>= 1) m = fmaxf(m, __shfl_xor_sync(0xffffffffu, m, o2));
    if (lane == 0) red[wid] = m;
    __syncthreads();
    if (tid == 0) {
        float mm = red[0];
        for (int w = 1; w < 8; w++) mm = fmaxf(mm, red[w]);
        red[8] = mm;
    }
    __syncthreads();
    m = red[8];
    __syncthreads();

    float sum = 0.f;
    for (int s = tid; s < Sn; s += 256) {
        float e = expf(sc[s] - m);
        sc[s] = e;
        sum += e;
    }
    #pragma unroll
    for (int o2 = 16; o2; o2 >>= 1) sum += __shfl_xor_sync(0xffffffffu, sum, o2);
    if (lane == 0) red[wid] = sum;
    __syncthreads();
    if (tid == 0) {
        float ss = 0.f;
        for (int w = 0; w < 8; w++) ss += red[w];
        red[9] = ss;
    }
    __syncthreads();
    float inv = 1.0f / red[9];
    for (int s = tid; s < Sn; s += 256) W[(size_t)b * Sn + s] = sc[s] * inv;
}

// ---------------- kernel 2: pooling partials (256MB streaming pass) ----------------
// NCH=16: 128 s-rows per block, 512 blocks; halves partial traffic vs NCH=32.
__global__ void k_pool_partial(const float* __restrict__ span,
                               const float* __restrict__ wa,
                               const float* __restrict__ wo,
                               float* __restrict__ pa, float* __restrict__ po) {
    int sc = blockIdx.x, b = blockIdx.y;
    __shared__ float swa[128], swo[128];
    int tid = threadIdx.x;  // 256
    if (tid < 128) swa[tid] = wa[(size_t)b * Sn + sc * 128 + tid];
    else { int t = tid - 128; swo[t] = wo[(size_t)b * Sn + sc * 128 + t]; }
    __syncthreads();

    const float4* base = (const float4*)(span + ((size_t)b * Sn + (size_t)sc * 128) * Hn);
    float4 aa = make_float4(0.f, 0.f, 0.f, 0.f);
    float4 oo = make_float4(0.f, 0.f, 0.f, 0.f);
    #pragma unroll 16
    for (int s = 0; s < 128; s++) {
        float4 v = __ldcs(base + (size_t)s * 256 + tid);   // streaming, evict-first
        float fa = swa[s], fo = swo[s];
        aa.x += v.x * fa; aa.y += v.y * fa; aa.z += v.z * fa; aa.w += v.w * fa;
        oo.x += v.x * fo; oo.y += v.y * fo; oo.z += v.z * fo; oo.w += v.w * fo;
    }
    size_t off = ((size_t)b * NCH + sc) * Hn + tid * 4;
    *(float4*)(pa + off) = aa;
    *(float4*)(po + off) = oo;
}

// ---------------- kernel 3: reduce partials -> embeddings + concat ----------------
__global__ void k_pool_reduce(const float* __restrict__ pa, const float* __restrict__ po,
                              float* __restrict__ aemb, float* __restrict__ oemb,
                              float* __restrict__ sin_) {
    int idx = blockIdx.x * 256 + threadIdx.x;  // 32768 total
    int b = idx >> 10, h = idx & 1023;
    float sa = 0.f, so = 0.f;
    #pragma unroll
    for (int c = 0; c < NCH; c++) {
        sa += pa[((size_t)b * NCH + c) * Hn + h];
        so += po[((size_t)b * NCH + c) * Hn + h];
    }
    aemb[idx] = sa;
    oemb[idx] = so;
    sin_[(size_t)b * 2048 + h] = sa;
    sin_[(size_t)b * 2048 + 1024 + h] = so;
}

// ---------------- kernel 4: register-tiled MLP GEMM (round-10 proven) ----------------
// Block: 32b x 128j over a 32-wide k-chunk, 256 threads, thread = 4b x 4j.
// W loads default policy: 14MB of weights stay L2-resident across graph replays.
struct GA { const float* x; const float* W; float* part; int K; int N; };

__global__ void __launch_bounds__(256) k_mlp_gemm(GA a0, GA a1, GA a2, int n0, int n01) {
    int bx = blockIdx.x;
    GA g;
    if (bx < n0) g = a0;
    else if (bx < n01) { g = a1; bx -= n0; }
    else { g = a2; bx -= n01; }
    int jt = g.N >> 7;             // 128-wide j-tiles
    int jtile = bx % jt;
    int kch   = bx / jt;
    int tid  = threadIdx.x;        // 256
    int lane = tid & 31;
    int wrp  = tid >> 5;           // 0..7, owns b rows [4w, 4w+4)
    int b0 = wrp << 2;
    int j  = (jtile << 7) + (lane << 2);
    int k0 = kch << 5;

    __shared__ float xs[32][33];   // xs[k][b], padded
    {
        int idx = tid;             // 256 threads cover 32x32 in 4 steps
        #pragma unroll
        for (int r = 0; r < 4; r++, idx += 256) {
            int b = idx >> 5, kk = idx & 31;
            xs[kk][b] = g.x[(size_t)b * g.K + k0 + kk];
        }
    }
    __syncthreads();

    float acc[4][4];
    #pragma unroll
    for (int bi = 0; bi < 4; bi++)
        #pragma unroll
        for (int ji = 0; ji < 4; ji++) acc[bi][ji] = 0.f;

    const float4* __restrict__ Wp = (const float4*)(g.W + (size_t)k0 * g.N + j);
    size_t stride4 = (size_t)(g.N >> 2);

    #pragma unroll
    for (int kk = 0; kk < 32; kk += 8) {
        float4 w[8];
        #pragma unroll
        for (int u = 0; u < 8; u++)
            w[u] = __ldg(Wp + (size_t)(kk + u) * stride4);   // default policy: L2-resident
        #pragma unroll
        for (int u = 0; u < 8; u++) {
            int k = kk + u;
            float xv0 = xs[k][b0 + 0];
            float xv1 = xs[k][b0 + 1];
            float xv2 = xs[k][b0 + 2];
            float xv3 = xs[k][b0 + 3];
            acc[0][0] += xv0 * w[u].x; acc[0][1] += xv0 * w[u].y; acc[0][2] += xv0 * w[u].z; acc[0][3] += xv0 * w[u].w;
            acc[1][0] += xv1 * w[u].x; acc[1][1] += xv1 * w[u].y; acc[1][2] += xv1 * w[u].z; acc[1][3] += xv1 * w[u].w;
            acc[2][0] += xv2 * w[u].x; acc[2][1] += xv2 * w[u].y; acc[2][2] += xv2 * w[u].z; acc[2][3] += xv2 * w[u].w;
            acc[3][0] += xv3 * w[u].x; acc[3][1] += xv3 * w[u].y; acc[3][2] += xv3 * w[u].z; acc[3][3] += xv3 * w[u].w;
        }
    }

    float* pp = g.part + (size_t)(kch * 32) * g.N + j;
    #pragma unroll
    for (int bi = 0; bi < 4; bi++) {
        float4 v = make_float4(acc[bi][0], acc[bi][1], acc[bi][2], acc[bi][3]);
        *(float4*)(pp + (size_t)(b0 + bi) * g.N) = v;
    }
}

// ---------------- kernel 5: combine partials + bias (+relu), float4 ----------------
struct CA { const float* part; const float* bias; float* out; int N; int kc; };

__global__ void k_combine(CA c0, CA c1, CA c2, int relu) {
    int idx = blockIdx.x * 256 + threadIdx.x;        // vec4 index
    int n0 = 32 * (c0.N >> 2), n1 = 32 * (c1.N >> 2), n2 = 32 * (c2.N >> 2);
    CA c;
    int li;
    if (idx < n0) { c = c0; li = idx; }
    else if (idx < n0 + n1) { c = c1; li = idx - n0; }
    else if (idx < n0 + n1 + n2) { c = c2; li = idx - n0 - n1; }
    else return;
    int nv = c.N >> 2;
    int b = li / nv, jv = li % nv;
    const float4* bias4 = (const float4*)c.bias;
    const float4* part4 = (const float4*)c.part;
    float4 s = bias4[jv];
    #pragma unroll 8
    for (int ch = 0; ch < c.kc; ch++) {
        float4 p = part4[(size_t)(ch * 32 + b) * nv + jv];
        s.x += p.x; s.y += p.y; s.z += p.z; s.w += p.w;
    }
    if (relu) {
        s.x = fmaxf(s.x, 0.f); s.y = fmaxf(s.y, 0.f);
        s.z = fmaxf(s.z, 0.f); s.w = fmaxf(s.w, 0.f);
    }
    ((float4*)c.out)[li] = s;
}

// ---------------- kernel 6: losses, 2 concurrent blocks ----------------
// block 0: InfoNCE(za, zo) -> res[0].  block 1: NT-Xent(zs) -> res[1].
__global__ void k_loss(const float* __restrict__ za, const float* __restrict__ zo,
                       const float* __restrict__ zs, const int* __restrict__ labels,
                       float* __restrict__ res) {
    __shared__ int lab[32];
    __shared__ float rowv[32];
    __shared__ float hasv[32];
    int tid = threadIdx.x;
    int i = tid >> 5, j = tid & 31;

    if (blockIdx.x == 0) {
        // ---- InfoNCE ----
        __shared__ float a[32][128];
        __shared__ float o[32][129];
        for (int idx = tid; idx < 32 * 128; idx += 1024) a[idx >> 7][idx & 127] = za[idx];
        for (int idx = tid; idx < 32 * 128; idx += 1024) o[idx >> 7][idx & 127] = zo[idx];
        if (tid < 32) lab[tid] = labels[tid];
        __syncthreads();

        {
            float sa = 0.f, so = 0.f;
            #pragma unroll
            for (int t = 0; t < 4; t++) {
                float va = a[i][j + 32 * t]; sa += va * va;
                float vo = o[i][j + 32 * t]; so += vo * vo;
            }
            #pragma unroll
            for (int o2 = 16; o2; o2 >>= 1) {
                sa += __shfl_xor_sync(0xffffffffu, sa, o2);
                so += __shfl_xor_sync(0xffffffffu, so, o2);
            }
            float ia = 1.0f / fmaxf(sqrtf(sa), 1e-12f);
            float io = 1.0f / fmaxf(sqrtf(so), 1e-12f);
            #pragma unroll
            for (int t = 0; t < 4; t++) {
                a[i][j + 32 * t] *= ia;
                o[i][j + 32 * t] *= io;
            }
        }
        __syncthreads();

        float d = 0.f;
        #pragma unroll 8
        for (int k = 0; k < 128; k++) d += a[i][k] * o[j][k];
        float e = expf(d * (1.0f / TEMP));
        bool same = (lab[i] == lab[j]);
        float pm = (i == j) ? 1.0f : (same ? 0.5f : 0.0f);
        float num = e * pm, den = e;
        #pragma unroll
        for (int o2 = 16; o2; o2 >>= 1) {
            num += __shfl_xor_sync(0xffffffffu, num, o2);
            den += __shfl_xor_sync(0xffffffffu, den, o2);
        }
        if (j == 0) rowv[i] = -logf(num / den + EPSL);
        __syncthreads();
        if (tid == 0) {
            float sm = 0.f;
            for (int r = 0; r < 32; r++) sm += rowv[r];
            res[0] = sm * (1.0f / 32.0f);
        }
    } else {
        // ---- NT-Xent ----
        __shared__ float s[32][257];
        for (int idx = tid; idx < 32 * 256; idx += 1024) s[idx >> 8][idx & 255] = zs[idx];
        if (tid < 32) lab[tid] = labels[tid];
        __syncthreads();

        {
            float ss = 0.f;
            #pragma unroll
            for (int t = 0; t < 8; t++) { float v = s[i][j + 32 * t]; ss += v * v; }
            #pragma unroll
            for (int o2 = 16; o2; o2 >>= 1) ss += __shfl_xor_sync(0xffffffffu, ss, o2);
            float inv = 1.0f / fmaxf(sqrtf(ss), 1e-12f);
            #pragma unroll
            for (int t = 0; t < 8; t++) s[i][j + 32 * t] *= inv;
        }
        __syncthreads();

        float d = 0.f;
        #pragma unroll 8
        for (int k = 0; k < 256; k++) d += s[i][k] * s[j][k];
        float e = expf(d * (1.0f / TEMP));
        bool same = (lab[i] == lab[j]);
        float maskv = (same && (i != j)) ? 1.0f : 0.0f;
        float pos = e * maskv;
        float neg = e * (1.0f - maskv);
        float cnt = maskv;
        #pragma unroll
        for (int o2 = 16; o2; o2 >>= 1) {
            pos += __shfl_xor_sync(0xffffffffu, pos, o2);
            neg += __shfl_xor_sync(0xffffffffu, neg, o2);
            cnt += __shfl_xor_sync(0xffffffffu, cnt, o2);
        }
        if (j == 0) {
            if (cnt > 0.f) {
                rowv[i] = -logf(pos / (pos + neg) + EPSL) / fmaxf(cnt, 1.0f);
                hasv[i] = 1.0f;
            } else {
                rowv[i] = 0.f;
                hasv[i] = 0.f;
            }
        }
        __syncthreads();
        if (tid == 0) {
            float sr = 0.f, sh = 0.f;
            for (int r = 0; r < 32; r++) { sr += rowv[r]; sh += hasv[r]; }
            res[1] = sr / fmaxf(sh, 1.0f);
        }
    }
}

// ---------------- kernel 7: final scalar ----------------
__global__ void k_final(const float* __restrict__ res, float* __restrict__ out) {
    out[0] = res[0] + 0.5f * res[1];
}

// ---------------- host launch ----------------
extern "C" void kernel_launch(void* const* d_in, const int* in_sizes, int n_in,
                              void* d_out, int out_size) {
    const float* span = (const float*)d_in[0];
    const float* la   = (const float*)d_in[1];
    const float* lo   = (const float*)d_in[2];
    const int*   lab  = (const int*)  d_in[3];
    const float* Wa1  = (const float*)d_in[4];
    const float* ba1  = (const float*)d_in[5];
    const float* Wa2  = (const float*)d_in[6];
    const float* ba2  = (const float*)d_in[7];
    const float* Wo1  = (const float*)d_in[8];
    const float* bo1  = (const float*)d_in[9];
    const float* Wo2  = (const float*)d_in[10];
    const float* bo2  = (const float*)d_in[11];
    const float* Ws1  = (const float*)d_in[12];
    const float* bs1  = (const float*)d_in[13];
    const float* Ws2  = (const float*)d_in[14];
    const float* bs2  = (const float*)d_in[15];
    float* out = (float*)d_out;

    float *p_wa, *p_wo, *p_pa, *p_po, *p_ae, *p_oe, *p_si, *p_gp;
    float *p_ha, *p_ho, *p_hs, *p_za, *p_zo, *p_zs, *p_res;
    cudaGetSymbolAddress((void**)&p_wa, g_wa);
    cudaGetSymbolAddress((void**)&p_wo, g_wo);
    cudaGetSymbolAddress((void**)&p_pa, g_pa);
    cudaGetSymbolAddress((void**)&p_po, g_po);
    cudaGetSymbolAddress((void**)&p_ae, g_aemb);
    cudaGetSymbolAddress((void**)&p_oe, g_oemb);
    cudaGetSymbolAddress((void**)&p_si, g_sin);
    cudaGetSymbolAddress((void**)&p_gp, g_gp);
    cudaGetSymbolAddress((void**)&p_ha, g_ha);
    cudaGetSymbolAddress((void**)&p_ho, g_ho);
    cudaGetSymbolAddress((void**)&p_hs, g_hs);
    cudaGetSymbolAddress((void**)&p_za, g_za);
    cudaGetSymbolAddress((void**)&p_zo, g_zo);
    cudaGetSymbolAddress((void**)&p_zs, g_zs);
    cudaGetSymbolAddress((void**)&p_res, g_res);

    // 1. softmax pooling weights
    k_softmax_w<<<dim3(32, 2), 256>>>(la, lo, p_wa, p_wo);

    // 2. pooled embeddings: one pass over the 256MB span tensor
    k_pool_partial<<<dim3(NCH, 32), 256>>>(span, p_wa, p_wo, p_pa, p_po);
    k_pool_reduce<<<128, 256>>>(p_pa, p_po, p_ae, p_oe, p_si);

    // 3. layer-1 GEMMs in one flattened launch (relu in combine)
    {
        GA a0 = {p_ae, Wa1, p_gp + G0OFF, 1024, 512};   // kc=32, jt=4 -> 128 blocks
        GA a1 = {p_oe, Wo1, p_gp + G1OFF, 1024, 512};   // 128
        GA a2 = {p_si, Ws1, p_gp + G2OFF, 2048, 1024};  // kc=64, jt=8 -> 512
        k_mlp_gemm<<<768, 256>>>(a0, a1, a2, 128, 256);
        CA c0 = {p_gp + G0OFF, ba1, p_ha, 512, 32};
        CA c1 = {p_gp + G1OFF, bo1, p_ho, 512, 32};
        CA c2 = {p_gp + G2OFF, bs1, p_hs, 1024, 64};
        k_combine<<<64, 256>>>(c0, c1, c2, 1);
    }

    // 4. layer-2 GEMMs in one flattened launch (bias only)
    {
        GA a0 = {p_ha, Wa2, p_gp + G0OFF, 512, 128};    // kc=16, jt=1 -> 16
        GA a1 = {p_ho, Wo2, p_gp + G1OFF, 512, 128};    // 16
        GA a2 = {p_hs, Ws2, p_gp + G2OFF, 1024, 256};   // kc=32, jt=2 -> 64
        k_mlp_gemm<<<96, 256>>>(a0, a1, a2, 16, 32);
        CA c0 = {p_gp + G0OFF, ba2, p_za, 128, 16};
        CA c1 = {p_gp + G1OFF, bo2, p_zo, 128, 16};
        CA c2 = {p_gp + G2OFF, bs2, p_zs, 256, 32};
        k_combine<<<16, 256>>>(c0, c1, c2, 0);
    }

    // 5. losses: 2 concurrent blocks, then final scalar
    k_loss<<<2, 1024>>>(p_za, p_zo, p_zs, lab, p_res);
    k_final<<<1, 1>>>(p_res, out);
}